// round 14
// baseline (speedup 1.0000x reference)
#include <cuda_runtime.h>
#include <cuda_fp16.h>
#include <cstdint>
#include <math.h>

#define NB 8
#define CI 128
#define CO 128
#define HH 64
#define WW 64
#define HW (HH * WW)
#define LT 128
#define NIT 108            // 9 taps * 4 chunks(32ch) * 3 branches
#define NTC 36             // 9 taps * 4 chunks
#define NTHR 256

#define RPK_BLK 1728
#define PPK_BLK 8192

#define SM_MSM   0                     // 27*128*4 = 13824
#define SM_WBUF  13824                 // 2 oq-groups * 2 bufs * 4096
#define SM_TOTAL (13824 + 2 * 8192)    // 30208

// Fragment-ready fp16 weights: [it(108)][khalf(2)][t(8)][lane(32)][r(4)][e(2)]
__device__ __align__(16) __half g_Wh[NIT * 4096];
// Pre-packed x: half2(x[2c2], x[2c2+1]) laid out [n][c2(64)][hw]
__device__ __align__(16) uint32_t g_Xh[NB * 64 * HW];

__global__ void prep_kernel(const float* __restrict__ x,
                            const float* __restrict__ w0,
                            const float* __restrict__ w1,
                            const float* __restrict__ w2) {
  int bid = blockIdx.x;
  if (bid < PPK_BLK) {
    int idx = bid * 256 + threadIdx.x;
    int hw = idx & (HW - 1);
    int c2 = (idx >> 12) & 63;
    int n  = idx >> 18;
    const float* xp = x + ((size_t)n * CI + 2 * c2) * HW + hw;
    __half2 p = __floats2half2_rn(xp[0], xp[HW]);
    g_Xh[idx] = *(uint32_t*)&p;
  } else {
    int idx = (bid - PPK_BLK) * 256 + threadIdx.x;
    int e    = idx & 1;
    int r    = (idx >> 1) & 3;
    int lane = (idx >> 3) & 31;
    int t    = (idx >> 8) & 7;
    int h    = (idx >> 11) & 1;
    int step = idx >> 12;
    int b  = step % 3;
    int tc = step / 3;
    int ch = tc & 3, tap = tc >> 2;
    int o = t * 16 + (lane >> 2) + 8 * (r & 1);
    int k = 2 * (lane & 3) + 8 * (r >> 1) + e;
    int c = ch * 32 + h * 16 + k;
    const float* w = (b == 0) ? w0 : ((b == 1) ? w1 : w2);
    g_Wh[idx] = __float2half_rn(w[(o * CI + c) * 9 + tap]);
  }
}

__device__ __forceinline__ void mma16816(float* c, const uint32_t* a,
                                         const uint32_t* b) {
  asm volatile(
      "mma.sync.aligned.m16n8k16.row.col.f32.f16.f16.f32 "
      "{%0,%1,%2,%3}, {%4,%5,%6,%7}, {%8,%9}, {%0,%1,%2,%3};"
      : "+f"(c[0]), "+f"(c[1]), "+f"(c[2]), "+f"(c[3])
      : "r"(a[0]), "r"(a[1]), "r"(a[2]), "r"(a[3]), "r"(b[0]), "r"(b[1]));
}
__device__ __forceinline__ uint32_t hmul2u(uint32_t a, uint32_t b) {
  __half2 r = __hmul2(*(__half2*)&a, *(__half2*)&b);
  return *(uint32_t*)&r;
}

__global__ __launch_bounds__(NTHR, 2) void conv25d_mma(
    const float* __restrict__ depth, const float* __restrict__ fx,
    float* __restrict__ out) {
  extern __shared__ __align__(16) char smem[];
  uint32_t* Msm = (uint32_t*)(smem + SM_MSM);

  const int tid = threadIdx.x;
  const int n   = blockIdx.y;
  const int l0  = blockIdx.x * LT;
  const int h0  = l0 >> 6;
  const uint32_t* xhn = g_Xh + (size_t)n * 64 * HW;
  const float* dn = depth + (size_t)n * HW;

  // ---- mask precompute (verified math), packed half2 ----
  if (tid < LT) {
    int l = tid, h = h0 + (l >> 6), w = l & 63;
    float d[9];
#pragma unroll
    for (int kh = 0; kh < 3; ++kh)
#pragma unroll
      for (int kw = 0; kw < 3; ++kw) {
        int hh2 = h + kh - 1, ww2 = w + kw - 1;
        bool ok = (((unsigned)hh2) < HH) && (((unsigned)ww2) < WW);
        d[kh * 3 + kw] = ok ? dn[hh2 * WW + ww2] : 0.f;
      }
    float fxn = fx[n];
    float cvalid = (d[4] != 0.f) ? 1.f : 0.f;
    float center = d[4] * cvalid;
    float grid = center / fxn;
    float half = 0.5f * grid;
#pragma unroll
    for (int k = 0; k < 9; ++k) {
      float vld = (d[k] != 0.f) ? cvalid : 0.f;
      float dm = d[k] * vld;
      float m0 = (fabsf(dm - (center + grid)) <= half) ? 1.f : 0.f;
      float m1 = (fabsf(dm - center) <= half) ? 1.f : 0.f;
      m1 = fminf(m1 + 1.f - vld, 1.f);
      float m2 = (fabsf(dm - (center - grid)) <= half) ? 1.f : 0.f;
      __half2 p0 = __float2half2_rn(m0), p1 = __float2half2_rn(m1),
              p2 = __float2half2_rn(m2);
      Msm[(k * 3 + 0) * LT + l] = *(uint32_t*)&p0;
      Msm[(k * 3 + 1) * LT + l] = *(uint32_t*)&p1;
      Msm[(k * 3 + 2) * LT + l] = *(uint32_t*)&p2;
    }
  }
  __syncthreads();

  const int lane = tid & 31;
  const int wq = tid >> 5;
  const int oq = wq >> 2, lq = wq & 3;      // warp tile: 64o x 32l
  const int g = lane >> 2, tig = lane & 3;
  const int lrow = lq >> 1;
  const int lcb  = (lq & 1) * 32;

  // SHARED A double buffer per oq-group (threads [oq*128, oq*128+128))
  char* wbuf = smem + SM_WBUF + oq * 8192;
  const uint32_t wbuf_s = (uint32_t)__cvta_generic_to_shared(wbuf);
  const char* wsrc = (const char*)g_Wh + (size_t)oq * 2048 + lane * 16;
  const int bar_id = 1 + oq;

  // each warp copies rows {lq*2, lq*2+1} of the group's 8-row branch tile
  auto acp = [&](int it, int bb) {
    const char* s = wsrc + (size_t)it * 8192;
    uint32_t d = wbuf_s + bb * 4096 + lane * 16;
#pragma unroll
    for (int t = 0; t < 2; ++t) {
      int r = lq * 2 + t;
      int srow = (r >> 2) * 4096 + (r & 3) * 512;
      asm volatile("cp.async.cg.shared.global [%0], [%1], 16;" ::"r"(
                       d + r * 512),
                   "l"(s + srow));
    }
    asm volatile("cp.async.commit_group;");
  };

  float acc[4][4][4];
#pragma unroll
  for (int i = 0; i < 4; ++i)
#pragma unroll
    for (int j = 0; j < 4; ++j)
#pragma unroll
      for (int r = 0; r < 4; ++r) acc[i][j][r] = 0.f;

  uint32_t xv[16];

  // prologue: group-cooperatively stage branch 0
  acp(0, 0);
  asm volatile("cp.async.wait_group 0;");
  asm volatile("bar.sync %0, 128;" ::"r"(bar_id) : "memory");

#pragma unroll 1
  for (int tc = 0; tc < NTC; ++tc) {
    int tap = tc >> 2, ch = tc & 3;
    int dy = tap / 3 - 1, dx = tap % 3 - 1;
    int hrow = h0 + lrow + dy;
    bool okh = ((unsigned)hrow) < HH;
    const uint32_t* rb = xhn + hrow * WW;

    // ---- load x fragment: 16 LDG.32 of pre-packed half2 ----
#pragma unroll
    for (int p = 0; p < 4; ++p) {
      int c2 = ch * 16 + (p >> 1) * 8 + (p & 1) * 4 + tig;
      const uint32_t* xp = rb + (size_t)c2 * HW;
#pragma unroll
      for (int j = 0; j < 4; ++j) {
        int w = lcb + j * 8 + g + dx;
        bool ok = okh && (((unsigned)w) < WW);
        xv[p * 4 + j] = ok ? __ldg(xp + w) : 0u;
      }
    }

    // ---- 3 branches reuse xv ----
#pragma unroll
    for (int b = 0; b < 3; ++b) {
      int it = tc * 3 + b;
      int s = tap * 3 + b;
      int bb = it & 1;

      // cooperatively stage next branch's A into the other buffer
      if (it + 1 < NIT) acp(it + 1, bb ^ 1);

      uint32_t msk[4];
#pragma unroll
      for (int j = 0; j < 4; ++j)
        msk[j] = Msm[s * LT + lq * 32 + j * 8 + g];

      const uint4* ab = (const uint4*)(wbuf + bb * 4096);
#pragma unroll
      for (int h = 0; h < 2; ++h) {
        uint32_t a[4][4];
#pragma unroll
        for (int i = 0; i < 4; ++i) {
          uint4 q = ab[(h * 4 + i) * 32 + lane];
          a[i][0] = q.x; a[i][1] = q.y; a[i][2] = q.z; a[i][3] = q.w;
        }
#pragma unroll
        for (int j = 0; j < 4; ++j) {
          uint32_t bbv[2];
          bbv[0] = hmul2u(xv[(h * 2 + 0) * 4 + j], msk[j]);
          bbv[1] = hmul2u(xv[(h * 2 + 1) * 4 + j], msk[j]);
#pragma unroll
          for (int i = 0; i < 4; ++i) mma16816(acc[i][j], a[i], bbv);
        }
      }

      if (it + 1 < NIT) {
        // own copies landed; then group barrier makes all 4 warps' visible
        asm volatile("cp.async.wait_group 0;");
        asm volatile("bar.sync %0, 128;" ::"r"(bar_id) : "memory");
      }

      // warm next chunk's x footprint during the middle branch
      if (b == 1 && tc + 1 < NTC) {
        int tcn = tc + 1, chn = tcn & 3, tapn = tcn >> 2;
        int dyn_ = tapn / 3 - 1;
        int hr = h0 + lrow + dyn_;
        if (((unsigned)hr) < HH && lane < 16) {
          const uint32_t* pa = xhn + (size_t)(chn * 16 + lane) * HW + hr * WW + lcb;
          asm volatile("prefetch.global.L1 [%0];" ::"l"(pa));
        }
      }
    }
  }

  // ---- epilogue (verified mapping) ----
  float* on = out + (size_t)n * CO * HW;
#pragma unroll
  for (int i = 0; i < 4; ++i) {
    int obase = oq * 64 + i * 16 + g;
#pragma unroll
    for (int j = 0; j < 4; ++j) {
      int lcol = l0 + lq * 32 + j * 8 + 2 * tig;
      float2 v0 = make_float2(acc[i][j][0], acc[i][j][1]);
      float2 v1 = make_float2(acc[i][j][2], acc[i][j][3]);
      *(float2*)&on[(size_t)obase * HW + lcol] = v0;
      *(float2*)&on[(size_t)(obase + 8) * HW + lcol] = v1;
    }
  }
}

extern "C" void kernel_launch(void* const* d_in, const int* in_sizes, int n_in,
                              void* d_out, int out_size) {
  const float* x     = (const float*)d_in[0];
  const float* depth = (const float*)d_in[1];
  const float* fx    = (const float*)d_in[2];
  const float* w0    = (const float*)d_in[3];
  const float* w1    = (const float*)d_in[4];
  const float* w2    = (const float*)d_in[5];
  float* out = (float*)d_out;

  cudaFuncSetAttribute(conv25d_mma,
                       cudaFuncAttributeMaxDynamicSharedMemorySize, SM_TOTAL);

  prep_kernel<<<RPK_BLK + PPK_BLK, 256>>>(x, w0, w1, w2);
  dim3 grid((HH * WW) / LT, NB);
  conv25d_mma<<<grid, NTHR, SM_TOTAL>>>(depth, fx, out);
}

// round 15
// speedup vs baseline: 1.0920x; 1.0920x over previous
#include <cuda_runtime.h>
#include <cuda_fp16.h>
#include <cstdint>
#include <math.h>

#define NB 8
#define CI 128
#define CO 128
#define HH 64
#define WW 64
#define HW (HH * WW)
#define LT 128
#define NIT 108            // 9 taps * 4 chunks(32ch) * 3 branches
#define NTC 36             // 9 taps * 4 chunks
#define NTHR 256

#define PPK_BLK 2048       // x prepack: NB*64*HW/4 elems / 256
#define RPK_BLK 1728       // weight repack: NIT*4096/256

#define SM_MSM   0                    // 27*128*4 = 13824
#define SM_WBUF  13824                // 8 warps * 2 * 4096
#define SM_TOTAL (13824 + 8 * 8192)   // 79360

// Fragment-ready fp16 weights: [it(108)][khalf(2)][t(8)][lane(32)][r(4)][e(2)]
__device__ __align__(16) __half g_Wh[NIT * 4096];
// Pre-packed x: half2(x[2c2], x[2c2+1]) laid out [n][c2(64)][hw]
__device__ __align__(16) uint32_t g_Xh[NB * 64 * HW];

__global__ void prep_kernel(const float* __restrict__ x,
                            const float* __restrict__ w0,
                            const float* __restrict__ w1,
                            const float* __restrict__ w2) {
  int bid = blockIdx.x;
  if (bid < PPK_BLK) {
    // x prepack, 4 hw positions per thread: 2x LDG.128 + 1x STG.128
    int t = bid * 256 + threadIdx.x;
    int hw4 = (t & 1023) << 2;
    int c2  = (t >> 10) & 63;
    int n   = t >> 16;
    const float4* xp0 = (const float4*)(x + ((size_t)n * CI + 2 * c2) * HW + hw4);
    const float4* xp1 = (const float4*)(x + ((size_t)n * CI + 2 * c2 + 1) * HW + hw4);
    float4 a = *xp0, b = *xp1;
    __half2 p0 = __floats2half2_rn(a.x, b.x);
    __half2 p1 = __floats2half2_rn(a.y, b.y);
    __half2 p2 = __floats2half2_rn(a.z, b.z);
    __half2 p3 = __floats2half2_rn(a.w, b.w);
    uint4 o = make_uint4(*(uint32_t*)&p0, *(uint32_t*)&p1,
                         *(uint32_t*)&p2, *(uint32_t*)&p3);
    *(uint4*)&g_Xh[((size_t)n * 64 + c2) * HW + hw4] = o;
  } else {
    int idx = (bid - PPK_BLK) * 256 + threadIdx.x;
    int e    = idx & 1;
    int r    = (idx >> 1) & 3;
    int lane = (idx >> 3) & 31;
    int t    = (idx >> 8) & 7;
    int h    = (idx >> 11) & 1;
    int step = idx >> 12;
    int b  = step % 3;
    int tc = step / 3;
    int ch = tc & 3, tap = tc >> 2;
    int o = t * 16 + (lane >> 2) + 8 * (r & 1);
    int k = 2 * (lane & 3) + 8 * (r >> 1) + e;
    int c = ch * 32 + h * 16 + k;
    const float* w = (b == 0) ? w0 : ((b == 1) ? w1 : w2);
    g_Wh[idx] = __float2half_rn(w[(o * CI + c) * 9 + tap]);
  }
}

__device__ __forceinline__ void mma16816(float* c, const uint32_t* a,
                                         const uint32_t* b) {
  asm volatile(
      "mma.sync.aligned.m16n8k16.row.col.f32.f16.f16.f32 "
      "{%0,%1,%2,%3}, {%4,%5,%6,%7}, {%8,%9}, {%0,%1,%2,%3};"
      : "+f"(c[0]), "+f"(c[1]), "+f"(c[2]), "+f"(c[3])
      : "r"(a[0]), "r"(a[1]), "r"(a[2]), "r"(a[3]), "r"(b[0]), "r"(b[1]));
}
__device__ __forceinline__ uint32_t hmul2u(uint32_t a, uint32_t b) {
  __half2 r = __hmul2(*(__half2*)&a, *(__half2*)&b);
  return *(uint32_t*)&r;
}

__global__ __launch_bounds__(NTHR, 2) void conv25d_mma(
    const float* __restrict__ depth, const float* __restrict__ fx,
    float* __restrict__ out) {
  extern __shared__ __align__(16) char smem[];
  uint32_t* Msm = (uint32_t*)(smem + SM_MSM);

  const int tid = threadIdx.x;
  const int n   = blockIdx.y;
  const int l0  = blockIdx.x * LT;
  const int h0  = l0 >> 6;
  const uint32_t* xhn = g_Xh + (size_t)n * 64 * HW;
  const float* dn = depth + (size_t)n * HW;

  // ---- mask precompute (verified math), packed half2 ----
  if (tid < LT) {
    int l = tid, h = h0 + (l >> 6), w = l & 63;
    float d[9];
#pragma unroll
    for (int kh = 0; kh < 3; ++kh)
#pragma unroll
      for (int kw = 0; kw < 3; ++kw) {
        int hh2 = h + kh - 1, ww2 = w + kw - 1;
        bool ok = (((unsigned)hh2) < HH) && (((unsigned)ww2) < WW);
        d[kh * 3 + kw] = ok ? dn[hh2 * WW + ww2] : 0.f;
      }
    float fxn = fx[n];
    float cvalid = (d[4] != 0.f) ? 1.f : 0.f;
    float center = d[4] * cvalid;
    float grid = center / fxn;
    float half = 0.5f * grid;
#pragma unroll
    for (int k = 0; k < 9; ++k) {
      float vld = (d[k] != 0.f) ? cvalid : 0.f;
      float dm = d[k] * vld;
      float m0 = (fabsf(dm - (center + grid)) <= half) ? 1.f : 0.f;
      float m1 = (fabsf(dm - center) <= half) ? 1.f : 0.f;
      m1 = fminf(m1 + 1.f - vld, 1.f);
      float m2 = (fabsf(dm - (center - grid)) <= half) ? 1.f : 0.f;
      __half2 p0 = __float2half2_rn(m0), p1 = __float2half2_rn(m1),
              p2 = __float2half2_rn(m2);
      Msm[(k * 3 + 0) * LT + l] = *(uint32_t*)&p0;
      Msm[(k * 3 + 1) * LT + l] = *(uint32_t*)&p1;
      Msm[(k * 3 + 2) * LT + l] = *(uint32_t*)&p2;
    }
  }
  __syncthreads();   // only barrier in the kernel

  const int lane = tid & 31;
  const int wq = tid >> 5;
  const int oq = wq >> 2, lq = wq & 3;      // warp tile: 64o x 32l
  const int g = lane >> 2, tig = lane & 3;
  const int lrow = lq >> 1;
  const int lcb  = (lq & 1) * 32;

  // warp-private A double buffer in smem
  char* wbuf = smem + SM_WBUF + wq * 8192;
  const uint32_t wbuf_s =
      (uint32_t)__cvta_generic_to_shared(wbuf) + lane * 16;
  const char* wsrc = (const char*)g_Wh + (size_t)oq * 2048 + lane * 16;

  auto acp = [&](int it, int bb) {
    const char* s = wsrc + (size_t)it * 8192;
    uint32_t d = wbuf_s + bb * 4096;
#pragma unroll
    for (int r = 0; r < 8; ++r) {
      int srow = (r >> 2) * 4096 + (r & 3) * 512;
      asm volatile("cp.async.cg.shared.global [%0], [%1], 16;" ::"r"(
                       d + r * 512),
                   "l"(s + srow));
    }
    asm volatile("cp.async.commit_group;");
  };

  float acc[4][4][4];
#pragma unroll
  for (int i = 0; i < 4; ++i)
#pragma unroll
    for (int j = 0; j < 4; ++j)
#pragma unroll
      for (int r = 0; r < 4; ++r) acc[i][j][r] = 0.f;

  uint32_t xv[16];

  // prologue: stage branch 0
  acp(0, 0);
  asm volatile("cp.async.wait_group 0;");

#pragma unroll 1
  for (int tc = 0; tc < NTC; ++tc) {
    int tap = tc >> 2, ch = tc & 3;
    int dy = tap / 3 - 1, dx = tap % 3 - 1;
    int hrow = h0 + lrow + dy;
    bool okh = ((unsigned)hrow) < HH;
    const uint32_t* rb = xhn + hrow * WW;

    // ---- load x fragment: 16 LDG.32 of pre-packed half2 ----
#pragma unroll
    for (int p = 0; p < 4; ++p) {
      int c2 = ch * 16 + (p >> 1) * 8 + (p & 1) * 4 + tig;
      const uint32_t* xp = rb + (size_t)c2 * HW;
#pragma unroll
      for (int j = 0; j < 4; ++j) {
        int w = lcb + j * 8 + g + dx;
        bool ok = okh && (((unsigned)w) < WW);
        xv[p * 4 + j] = ok ? __ldg(xp + w) : 0u;
      }
    }

    // ---- 3 branches reuse xv ----
#pragma unroll
    for (int b = 0; b < 3; ++b) {
      int it = tc * 3 + b;
      int s = tap * 3 + b;
      int bb = it & 1;

      // stage next branch's A while computing this one
      if (it + 1 < NIT) acp(it + 1, bb ^ 1);

      uint32_t msk[4];
#pragma unroll
      for (int j = 0; j < 4; ++j)
        msk[j] = Msm[s * LT + lq * 32 + j * 8 + g];

      const uint4* ab = (const uint4*)(wbuf + bb * 4096);
#pragma unroll
      for (int h = 0; h < 2; ++h) {
        uint32_t a[4][4];
#pragma unroll
        for (int i = 0; i < 4; ++i) {
          uint4 q = ab[(h * 4 + i) * 32 + lane];
          a[i][0] = q.x; a[i][1] = q.y; a[i][2] = q.z; a[i][3] = q.w;
        }
#pragma unroll
        for (int j = 0; j < 4; ++j) {
          uint32_t bbv[2];
          bbv[0] = hmul2u(xv[(h * 2 + 0) * 4 + j], msk[j]);
          bbv[1] = hmul2u(xv[(h * 2 + 1) * 4 + j], msk[j]);
#pragma unroll
          for (int i = 0; i < 4; ++i) mma16816(acc[i][j], a[i], bbv);
        }
      }

      // next branch's copy has had a full branch of shadow; drain it now
      asm volatile("cp.async.wait_group 0;");

      // warm next chunk's x footprint during the middle branch
      if (b == 1 && tc + 1 < NTC) {
        int tcn = tc + 1, chn = tcn & 3, tapn = tcn >> 2;
        int dyn_ = tapn / 3 - 1;
        int hr = h0 + lrow + dyn_;
        if (((unsigned)hr) < HH && lane < 16) {
          const uint32_t* pa = xhn + (size_t)(chn * 16 + lane) * HW + hr * WW + lcb;
          asm volatile("prefetch.global.L1 [%0];" ::"l"(pa));
        }
      }
    }
  }

  // ---- epilogue (verified mapping) ----
  float* on = out + (size_t)n * CO * HW;
#pragma unroll
  for (int i = 0; i < 4; ++i) {
    int obase = oq * 64 + i * 16 + g;
#pragma unroll
    for (int j = 0; j < 4; ++j) {
      int lcol = l0 + lq * 32 + j * 8 + 2 * tig;
      float2 v0 = make_float2(acc[i][j][0], acc[i][j][1]);
      float2 v1 = make_float2(acc[i][j][2], acc[i][j][3]);
      *(float2*)&on[(size_t)obase * HW + lcol] = v0;
      *(float2*)&on[(size_t)(obase + 8) * HW + lcol] = v1;
    }
  }
}

extern "C" void kernel_launch(void* const* d_in, const int* in_sizes, int n_in,
                              void* d_out, int out_size) {
  const float* x     = (const float*)d_in[0];
  const float* depth = (const float*)d_in[1];
  const float* fx    = (const float*)d_in[2];
  const float* w0    = (const float*)d_in[3];
  const float* w1    = (const float*)d_in[4];
  const float* w2    = (const float*)d_in[5];
  float* out = (float*)d_out;

  cudaFuncSetAttribute(conv25d_mma,
                       cudaFuncAttributeMaxDynamicSharedMemorySize, SM_TOTAL);

  prep_kernel<<<PPK_BLK + RPK_BLK, 256>>>(x, w0, w1, w2);
  dim3 grid((HH * WW) / LT, NB);
  conv25d_mma<<<grid, NTHR, SM_TOTAL>>>(depth, fx, out);
}